// round 1
// baseline (speedup 1.0000x reference)
#include <cuda_runtime.h>
#include <mma.h>
#include <cstdint>

using namespace nvcuda;

#define T_STEPS 1024
#define B_SZ    64
#define D_INSZ  1024
#define H_SZ    1024
#define BH      (B_SZ * H_SZ)          /* 65536 */
#define TBH     (T_STEPS * BH)         /* 67108864 */

// ---------------- scan config ----------------
#define NB   64          // persistent blocks (each owns JW output columns)
#define JW   16          // columns per block  (NB*JW == H_SZ)
#define KC   128         // k-chunk staged in smem
#define NCH  (H_SZ / KC) // 8 chunks per step

// ---------------------------------------------------------------------------
// Kernel A: xproj = xs @ Wih   (bias folded into scan epilogue)
// M = T*B = 65536, N = H = 1024, K = D = 1024.  tf32 wmma, 128x64x32 tiles.
// ---------------------------------------------------------------------------
__global__ void __launch_bounds__(256) xproj_gemm(const float* __restrict__ xs,
                                                  const float* __restrict__ Wih,
                                                  float* __restrict__ C) {
    __shared__ float As[128][32];
    __shared__ float Bs[32][64];

    const int tid = threadIdx.x;
    const int m0  = blockIdx.y * 128;
    const int n0  = blockIdx.x * 64;
    const int warp = tid >> 5;
    const int wm   = warp >> 1;   // 0..3
    const int wn   = warp & 1;    // 0..1

    wmma::fragment<wmma::accumulator, 16, 16, 8, float> cf[2][2];
#pragma unroll
    for (int i = 0; i < 2; i++)
#pragma unroll
        for (int j = 0; j < 2; j++) wmma::fill_fragment(cf[i][j], 0.0f);

    for (int kt = 0; kt < D_INSZ; kt += 32) {
#pragma unroll
        for (int i = 0; i < 4; i++) {
            int s = tid + i * 256;           // 0..1023
            int r = s >> 3, q = (s & 7) * 4;
            float4 v = *reinterpret_cast<const float4*>(
                xs + (size_t)(m0 + r) * D_INSZ + kt + q);
            As[r][q + 0] = wmma::__float_to_tf32(v.x);
            As[r][q + 1] = wmma::__float_to_tf32(v.y);
            As[r][q + 2] = wmma::__float_to_tf32(v.z);
            As[r][q + 3] = wmma::__float_to_tf32(v.w);
        }
#pragma unroll
        for (int i = 0; i < 2; i++) {
            int s = tid + i * 256;           // 0..511
            int r = s >> 4, q = (s & 15) * 4;
            float4 v = *reinterpret_cast<const float4*>(
                Wih + (size_t)(kt + r) * H_SZ + n0 + q);
            Bs[r][q + 0] = wmma::__float_to_tf32(v.x);
            Bs[r][q + 1] = wmma::__float_to_tf32(v.y);
            Bs[r][q + 2] = wmma::__float_to_tf32(v.z);
            Bs[r][q + 3] = wmma::__float_to_tf32(v.w);
        }
        __syncthreads();

#pragma unroll
        for (int kk = 0; kk < 4; kk++) {
            wmma::fragment<wmma::matrix_a, 16, 16, 8, wmma::precision::tf32, wmma::row_major> af[2];
            wmma::fragment<wmma::matrix_b, 16, 16, 8, wmma::precision::tf32, wmma::row_major> bf[2];
            wmma::load_matrix_sync(af[0], &As[wm * 32 + 0][kk * 8], 32);
            wmma::load_matrix_sync(af[1], &As[wm * 32 + 16][kk * 8], 32);
            wmma::load_matrix_sync(bf[0], &Bs[kk * 8][wn * 32 + 0], 64);
            wmma::load_matrix_sync(bf[1], &Bs[kk * 8][wn * 32 + 16], 64);
#pragma unroll
            for (int i = 0; i < 2; i++)
#pragma unroll
                for (int j = 0; j < 2; j++)
                    wmma::mma_sync(cf[i][j], af[i], bf[j], cf[i][j]);
        }
        __syncthreads();
    }

#pragma unroll
    for (int i = 0; i < 2; i++)
#pragma unroll
        for (int j = 0; j < 2; j++)
            wmma::store_matrix_sync(
                C + (size_t)(m0 + wm * 32 + i * 16) * H_SZ + n0 + wn * 32 + j * 16,
                cf[i][j], H_SZ, wmma::mem_row_major);
}

// ---------------------------------------------------------------------------
// Grid barrier (generation counting; replay-safe across graph launches)
// ---------------------------------------------------------------------------
__device__ unsigned g_count = 0;
__device__ volatile unsigned g_gen = 0;

__device__ __forceinline__ void grid_barrier(unsigned base, int step) {
    __syncthreads();
    if (threadIdx.x == 0) {
        __threadfence();
        unsigned old = atomicAdd(&g_count, 1u);
        if (old == NB - 1) {
            g_count = 0;
            __threadfence();
            g_gen = base + (unsigned)step + 1u;
        } else {
            while ((unsigned)(g_gen - base) < (unsigned)(step + 1)) { __nanosleep(32); }
            __threadfence();
        }
    }
    __syncthreads();
}

// ---------------------------------------------------------------------------
// Kernel B: persistent RNN scan.
// Block b owns columns [b*JW, b*JW+JW). Whh slice lives in SMEM for all steps.
// outs[] holds xproj before step t, h_t after. h_{t-1} read via __ldcg (L2).
// ---------------------------------------------------------------------------
__device__ __forceinline__ void loadChunk(float4* rg, const float* __restrict__ hp, int c) {
#pragma unroll
    for (int i = 0; i < 16; i++) {
        int s = threadIdx.x + i * 128;       // 0..2047
        int r = s >> 5, q = (s & 31) * 4;
        rg[i] = __ldcg(reinterpret_cast<const float4*>(hp + (size_t)r * H_SZ + c * KC + q));
    }
}

__device__ __forceinline__ void storeChunk(const float4* rg, float* hb) {
#pragma unroll
    for (int i = 0; i < 16; i++) {
        int s = threadIdx.x + i * 128;
        int r = s >> 5, q = (s & 31) * 4;
        float* d = hb + r * KC + q;
        d[0] = wmma::__float_to_tf32(rg[i].x);
        d[1] = wmma::__float_to_tf32(rg[i].y);
        d[2] = wmma::__float_to_tf32(rg[i].z);
        d[3] = wmma::__float_to_tf32(rg[i].w);
    }
}

__global__ void __launch_bounds__(128) rnn_scan(const float* __restrict__ init,
                                                const float* __restrict__ Whh,
                                                const float* __restrict__ bih,
                                                const float* __restrict__ bhh,
                                                float* __restrict__ outs) {
    extern __shared__ float sm[];
    float* WhhS  = sm;                          // H_SZ * JW          (16384 f)
    float* HS    = sm + H_SZ * JW;              // 2 * B_SZ * KC      (16384 f)
    float* stage = HS + 2 * B_SZ * KC;          // B_SZ * JW          (1024 f)

    const int tid = threadIdx.x;
    const int wm  = tid >> 5;                   // warp -> 16 batch rows
    const int j0  = blockIdx.x * JW;
    const unsigned base = g_gen;                // replay-safe barrier base

    const int jj = tid & (JW - 1);
    const float bsum = bih[j0 + jj] + bhh[j0 + jj];

    // Load persistent Whh column slice (tf32-pretruncated)
#pragma unroll
    for (int i = 0; i < 32; i++) {
        int s = tid + i * 128;                  // 0..4095
        int r = s >> 2, q = (s & 3) * 4;
        float4 v = *reinterpret_cast<const float4*>(Whh + (size_t)r * H_SZ + j0 + q);
        WhhS[r * JW + q + 0] = wmma::__float_to_tf32(v.x);
        WhhS[r * JW + q + 1] = wmma::__float_to_tf32(v.y);
        WhhS[r * JW + q + 2] = wmma::__float_to_tf32(v.z);
        WhhS[r * JW + q + 3] = wmma::__float_to_tf32(v.w);
    }
    __syncthreads();

#pragma unroll 1
    for (int t = 0; t < T_STEPS; t++) {
        const float* hprev = (t == 0) ? init : (outs + (size_t)(t - 1) * BH);

        float4 rg[16];
        loadChunk(rg, hprev, 0);
        storeChunk(rg, HS);
        __syncthreads();

        wmma::fragment<wmma::accumulator, 16, 16, 8, float> cf;
        wmma::fill_fragment(cf, 0.0f);

#pragma unroll 1
        for (int c = 0; c < NCH; c++) {
            if (c + 1 < NCH) loadChunk(rg, hprev, c + 1);   // overlap with mma
            const float* hb = HS + (c & 1) * (B_SZ * KC);
#pragma unroll
            for (int kk = 0; kk < KC / 8; kk++) {
                wmma::fragment<wmma::matrix_a, 16, 16, 8, wmma::precision::tf32, wmma::row_major> af;
                wmma::fragment<wmma::matrix_b, 16, 16, 8, wmma::precision::tf32, wmma::row_major> bf;
                wmma::load_matrix_sync(af, hb + (wm * 16) * KC + kk * 8, KC);
                wmma::load_matrix_sync(bf, WhhS + (c * KC + kk * 8) * JW, JW);
                wmma::mma_sync(cf, af, bf, cf);
            }
            if (c + 1 < NCH) {
                storeChunk(rg, HS + ((c + 1) & 1) * (B_SZ * KC));
                __syncthreads();
            }
        }

        wmma::store_matrix_sync(stage + wm * 16 * JW, cf, JW, wmma::mem_row_major);
        __syncthreads();

        // epilogue: h = tanh(hWhh + xproj + bih + bhh); overwrite xproj in-place
#pragma unroll
        for (int i = 0; i < 8; i++) {
            int s = tid + i * 128;               // 0..1023
            int r = s >> 4;                      // batch row
            size_t off = (size_t)t * BH + (size_t)r * H_SZ + j0 + jj;
            float xp = __ldcg(outs + off);
            outs[off] = tanhf(stage[s] + xp + bsum);
        }

        grid_barrier(base, t);
    }
}

// ---------------------------------------------------------------------------
__global__ void copy_carry(float* __restrict__ dst, const float* __restrict__ src) {
    int i = blockIdx.x * blockDim.x + threadIdx.x;
    dst[i] = src[i];
}

// ---------------------------------------------------------------------------
extern "C" void kernel_launch(void* const* d_in, const int* in_sizes, int n_in,
                              void* d_out, int out_size) {
    const float* init = (const float*)d_in[0];
    const float* xs   = (const float*)d_in[1];
    const float* Wih  = (const float*)d_in[2];
    const float* bih  = (const float*)d_in[3];
    const float* Whh  = (const float*)d_in[4];
    const float* bhh  = (const float*)d_in[5];

    float* out   = (float*)d_out;
    float* carry = nullptr;
    float* outs;
    if (out_size == BH + TBH) { carry = out; outs = out + BH; }
    else                      { outs = out; }

    // 1) xproj = xs @ Wih   (written into outs region, in-place scratch)
    xproj_gemm<<<dim3(H_SZ / 64, (T_STEPS * B_SZ) / 128), 256>>>(xs, Wih, outs);

    // 2) persistent recurrent scan
    int smem = (H_SZ * JW + 2 * B_SZ * KC + B_SZ * JW) * (int)sizeof(float);
    cudaFuncSetAttribute(rnn_scan, cudaFuncAttributeMaxDynamicSharedMemorySize, smem);
    rnn_scan<<<NB, 128, smem>>>(init, Whh, bih, bhh, outs);

    // 3) carry = h_{T-1}
    if (carry)
        copy_carry<<<BH / 256, 256>>>(carry, outs + (size_t)(T_STEPS - 1) * BH);
}

// round 2
// speedup vs baseline: 3.2578x; 3.2578x over previous
#include <cuda_runtime.h>
#include <mma.h>
#include <cstdint>

using namespace nvcuda;

#define T_STEPS 1024
#define B_SZ    64
#define H_SZ    1024
#define BH      (B_SZ * H_SZ)          /* 65536 */
#define TBH     (T_STEPS * BH)         /* 67108864 */

// ---------------- scan config ----------------
#define RSZ  16          // batch rows per block
#define CSZ  32          // output cols per block
#define NBLK 128         // (64/RSZ) * (1024/CSZ) = 4 * 32
#define KCH  128         // k-chunk size
#define NCH  8           // chunks per step
#define AST  132         // h chunk smem row stride (pad)
#define WST  36          // Whh smem row stride (pad)

__device__ unsigned g_flags[NBLK];

// ---------------- cp.async helpers ----------------
__device__ __forceinline__ void cp16(float* s, const float* g) {
    unsigned sa = (unsigned)__cvta_generic_to_shared(s);
    asm volatile("cp.async.cg.shared.global [%0], [%1], 16;" :: "r"(sa), "l"(g));
}
__device__ __forceinline__ void cpcommit() { asm volatile("cp.async.commit_group;"); }
template<int N> __device__ __forceinline__ void cpwait() {
    asm volatile("cp.async.wait_group %0;" :: "n"(N));
}

// ---------------------------------------------------------------------------
// Kernel A: xproj = xs @ Wih  (bias folded into scan epilogue)
// 128x128x32 tiles, tf32 wmma, register double-buffered global loads.
// ---------------------------------------------------------------------------
__global__ void __launch_bounds__(256) xproj_gemm(const float* __restrict__ xs,
                                                  const float* __restrict__ Wih,
                                                  float* __restrict__ C) {
    __shared__ float As[128 * 36];
    __shared__ float Bs[32 * 136];

    const int tid = threadIdx.x;
    const int m0  = blockIdx.y * 128;
    const int n0  = blockIdx.x * 128;
    const int w   = tid >> 5;
    const int wm  = w >> 1;   // 0..3 -> 32 rows each
    const int wn  = w & 1;    // 0..1 -> 64 cols each

    wmma::fragment<wmma::accumulator, 16, 16, 8, float> cf[2][4];
#pragma unroll
    for (int i = 0; i < 2; i++)
#pragma unroll
        for (int j = 0; j < 4; j++) wmma::fill_fragment(cf[i][j], 0.0f);

    float4 a4[4], b4[4];
    // prefetch k-tile 0
#pragma unroll
    for (int i = 0; i < 4; i++) {
        int idx = tid + i * 256;
        int r = idx >> 3, q = (idx & 7) * 4;
        a4[i] = *reinterpret_cast<const float4*>(xs + (size_t)(m0 + r) * H_SZ + q);
    }
#pragma unroll
    for (int i = 0; i < 4; i++) {
        int idx = tid + i * 256;
        int r = idx >> 5, q = (idx & 31) * 4;
        b4[i] = *reinterpret_cast<const float4*>(Wih + (size_t)r * H_SZ + n0 + q);
    }

    for (int kt = 0; kt < H_SZ; kt += 32) {
        // stage regs -> smem (rounded to tf32)
#pragma unroll
        for (int i = 0; i < 4; i++) {
            int idx = tid + i * 256;
            int r = idx >> 3, q = (idx & 7) * 4;
            float4 o;
            o.x = wmma::__float_to_tf32(a4[i].x);
            o.y = wmma::__float_to_tf32(a4[i].y);
            o.z = wmma::__float_to_tf32(a4[i].z);
            o.w = wmma::__float_to_tf32(a4[i].w);
            *reinterpret_cast<float4*>(As + r * 36 + q) = o;
        }
#pragma unroll
        for (int i = 0; i < 4; i++) {
            int idx = tid + i * 256;
            int r = idx >> 5, q = (idx & 31) * 4;
            float4 o;
            o.x = wmma::__float_to_tf32(b4[i].x);
            o.y = wmma::__float_to_tf32(b4[i].y);
            o.z = wmma::__float_to_tf32(b4[i].z);
            o.w = wmma::__float_to_tf32(b4[i].w);
            *reinterpret_cast<float4*>(Bs + r * 136 + q) = o;
        }
        __syncthreads();

        if (kt + 32 < H_SZ) {
#pragma unroll
            for (int i = 0; i < 4; i++) {
                int idx = tid + i * 256;
                int r = idx >> 3, q = (idx & 7) * 4;
                a4[i] = *reinterpret_cast<const float4*>(
                    xs + (size_t)(m0 + r) * H_SZ + kt + 32 + q);
            }
#pragma unroll
            for (int i = 0; i < 4; i++) {
                int idx = tid + i * 256;
                int r = idx >> 5, q = (idx & 31) * 4;
                b4[i] = *reinterpret_cast<const float4*>(
                    Wih + (size_t)(kt + 32 + r) * H_SZ + n0 + q);
            }
        }

#pragma unroll
        for (int kk = 0; kk < 4; kk++) {
            wmma::fragment<wmma::matrix_a, 16, 16, 8, wmma::precision::tf32, wmma::row_major> af[2];
            wmma::fragment<wmma::matrix_b, 16, 16, 8, wmma::precision::tf32, wmma::row_major> bf[4];
            wmma::load_matrix_sync(af[0], As + (wm * 32 + 0)  * 36 + kk * 8, 36);
            wmma::load_matrix_sync(af[1], As + (wm * 32 + 16) * 36 + kk * 8, 36);
#pragma unroll
            for (int j = 0; j < 4; j++)
                wmma::load_matrix_sync(bf[j], Bs + (kk * 8) * 136 + wn * 64 + j * 16, 136);
#pragma unroll
            for (int i = 0; i < 2; i++)
#pragma unroll
                for (int j = 0; j < 4; j++)
                    wmma::mma_sync(cf[i][j], af[i], bf[j], cf[i][j]);
        }
        __syncthreads();
    }

#pragma unroll
    for (int i = 0; i < 2; i++)
#pragma unroll
        for (int j = 0; j < 4; j++)
            wmma::store_matrix_sync(
                C + (size_t)(m0 + wm * 32 + i * 16) * H_SZ + n0 + wn * 64 + j * 16,
                cf[i][j], H_SZ, wmma::mem_row_major);
}

// ---------------------------------------------------------------------------
// Kernel B: persistent RNN scan, flag-synchronized, cp.async pipelined.
// Block bid: rb = bid&3 (16 batch rows), jb = bid>>2 (32 output cols).
// Row groups are fully independent (batch dim is parallel).
// outs[t] holds xproj before step t, tf32-rounded h after.
// ---------------------------------------------------------------------------
__global__ void __launch_bounds__(256) rnn_scan(const float* __restrict__ init,
                                                const float* __restrict__ Whh,
                                                const float* __restrict__ bih,
                                                const float* __restrict__ bhh,
                                                float* __restrict__ outs,
                                                float* __restrict__ carry) {
    extern __shared__ float sm[];
    float* WhhS  = sm;                           // 1024*36 = 36864 f
    float* bufs  = WhhS + H_SZ * WST;            // 4 * 16*132 = 8448 f
    float* stage = bufs + 4 * RSZ * AST;         // 4 * 16*32 = 2048 f
    float* xpS   = stage + 4 * RSZ * CSZ;        // 16*32 = 512 f

    const int tid = threadIdx.x, bid = blockIdx.x;
    const int rb = bid & 3, jb = bid >> 2;
    const int r0 = rb * RSZ, j0 = jb * CSZ;
    const int w = tid >> 5, lane = tid & 31;
    const int nj = w & 1;      // col 16-tile
    const int kq = w >> 1;     // kk mod 4 slice

    const unsigned base = __ldcg(&g_flags[bid]);    // replay-safe epoch
    const float bsum = bih[j0 + lane] + bhh[j0 + lane];

    // Load persistent Whh column slice (rounded to tf32)
#pragma unroll
    for (int i = 0; i < 32; i++) {
        int idx = tid + i * 256;
        int r = idx >> 3, q = (idx & 7) * 4;
        float4 v = *reinterpret_cast<const float4*>(Whh + (size_t)r * H_SZ + j0 + q);
        float4 o;
        o.x = wmma::__float_to_tf32(v.x);
        o.y = wmma::__float_to_tf32(v.y);
        o.z = wmma::__float_to_tf32(v.z);
        o.w = wmma::__float_to_tf32(v.w);
        *reinterpret_cast<float4*>(WhhS + r * WST + q) = o;
    }
    __syncthreads();

#pragma unroll 1
    for (int t = 0; t < T_STEPS; t++) {
        const float* hsrc = t ? (outs + (size_t)(t - 1) * BH) : init;

        // wait for all 32 same-row producers to have published h[t-1]
        if (w == 0) {
            const unsigned p = ((unsigned)lane << 2) | (unsigned)rb;
            while ((int)(__ldcg(&g_flags[p]) - base) < t) { __nanosleep(40); }
            __threadfence();
        }
        __syncthreads();

        // G0: xproj tile + h chunk 0 ; G1: chunk 1 ; G2: chunk 2
        if (tid < 128) {
            int r = tid >> 3, u = tid & 7;
            cp16(xpS + r * CSZ + u * 4,
                 outs + (size_t)t * BH + (size_t)(r0 + r) * H_SZ + j0 + u * 4);
        }
#pragma unroll
        for (int c0 = 0; c0 < 3; c0++) {
            float* buf = bufs + c0 * (RSZ * AST);
#pragma unroll
            for (int i = 0; i < 2; i++) {
                int idx = tid + i * 256;
                int r = idx >> 5, u = idx & 31;
                cp16(buf + r * AST + u * 4,
                     hsrc + (size_t)(r0 + r) * H_SZ + c0 * KCH + u * 4);
            }
            cpcommit();
        }

        wmma::fragment<wmma::accumulator, 16, 16, 8, float> cf;
        wmma::fill_fragment(cf, 0.0f);

#pragma unroll
        for (int c = 0; c < NCH; c++) {
            if (c <= 5) cpwait<2>(); else if (c == 6) cpwait<1>(); else cpwait<0>();
            __syncthreads();

            if (c + 3 < NCH) {
                float* buf = bufs + ((c + 3) & 3) * (RSZ * AST);
#pragma unroll
                for (int i = 0; i < 2; i++) {
                    int idx = tid + i * 256;
                    int r = idx >> 5, u = idx & 31;
                    cp16(buf + r * AST + u * 4,
                         hsrc + (size_t)(r0 + r) * H_SZ + (c + 3) * KCH + u * 4);
                }
                cpcommit();
            }

            const float* buf = bufs + (c & 3) * (RSZ * AST);
#pragma unroll
            for (int m = 0; m < 4; m++) {
                const int kk = kq + m * 4;
                wmma::fragment<wmma::matrix_a, 16, 16, 8, wmma::precision::tf32, wmma::row_major> af;
                wmma::fragment<wmma::matrix_b, 16, 16, 8, wmma::precision::tf32, wmma::row_major> bf;
                wmma::load_matrix_sync(af, buf + kk * 8, AST);
                wmma::load_matrix_sync(bf, WhhS + (c * KCH + kk * 8) * WST + nj * 16, WST);
                wmma::mma_sync(cf, af, bf, cf);
            }
        }

        wmma::store_matrix_sync(stage + kq * (RSZ * CSZ) + nj * 16, cf, CSZ,
                                wmma::mem_row_major);
        __syncthreads();

        // epilogue: h = tf32(tanh(sum_partials + xproj + bias)); in-place store
#pragma unroll
        for (int i = 0; i < 2; i++) {
            int s = tid + i * 256;
            int r = s >> 5;
            float v = stage[r * CSZ + lane]
                    + stage[RSZ * CSZ + r * CSZ + lane]
                    + stage[2 * RSZ * CSZ + r * CSZ + lane]
                    + stage[3 * RSZ * CSZ + r * CSZ + lane]
                    + xpS[r * CSZ + lane] + bsum;
            v = wmma::__float_to_tf32(tanhf(v));
            size_t off = (size_t)t * BH + (size_t)(r0 + r) * H_SZ + j0 + lane;
            outs[off] = v;
            if (carry != nullptr && t == T_STEPS - 1)
                carry[(size_t)(r0 + r) * H_SZ + j0 + lane] = v;
        }
        __syncthreads();

        if (tid == 0) {
            __threadfence();
            atomicExch(&g_flags[bid], base + (unsigned)(t + 1));
        }
    }
}

// ---------------------------------------------------------------------------
extern "C" void kernel_launch(void* const* d_in, const int* in_sizes, int n_in,
                              void* d_out, int out_size) {
    const float* init = (const float*)d_in[0];
    const float* xs   = (const float*)d_in[1];
    const float* Wih  = (const float*)d_in[2];
    const float* bih  = (const float*)d_in[3];
    const float* Whh  = (const float*)d_in[4];
    const float* bhh  = (const float*)d_in[5];

    float* out   = (float*)d_out;
    float* carry = nullptr;
    float* outs;
    if (out_size == BH + TBH) { carry = out; outs = out + BH; }
    else                      { outs = out; }

    // 1) xproj = xs @ Wih  (into outs, consumed in-place by the scan)
    xproj_gemm<<<dim3(H_SZ / 128, (T_STEPS * B_SZ) / 128), 256>>>(xs, Wih, outs);

    // 2) persistent flag-synchronized scan (fuses carry write at t=T-1)
    int smem = (H_SZ * WST + 4 * RSZ * AST + 4 * RSZ * CSZ + RSZ * CSZ) * (int)sizeof(float);
    cudaFuncSetAttribute(rnn_scan, cudaFuncAttributeMaxDynamicSharedMemorySize, smem);
    rnn_scan<<<NBLK, 256, smem>>>(init, Whh, bih, bhh, outs, carry);
}

// round 3
// speedup vs baseline: 3.7130x; 1.1397x over previous
#include <cuda_runtime.h>
#include <mma.h>
#include <cstdint>

using namespace nvcuda;

#define T_STEPS 1024
#define B_SZ    64
#define H_SZ    1024
#define BH      (B_SZ * H_SZ)          /* 65536 */
#define TBH     (T_STEPS * BH)         /* 67108864 */

// ---------------- scan config ----------------
#define RSZ  16          // batch rows per block
#define CSZ  32          // output cols per block
#define NBLK 128         // (64/RSZ) * (1024/CSZ)
#define KCH  128         // k-chunk (one per warp)
#define NCH  8
#define AST  132         // h chunk smem row stride (pad)
#define WST  36          // Whh smem row stride (pad)

__device__ unsigned g_flags[NBLK];

// ---------------- asm helpers ----------------
__device__ __forceinline__ void cp16(float* s, const float* g) {
    unsigned sa = (unsigned)__cvta_generic_to_shared(s);
    asm volatile("cp.async.cg.shared.global [%0], [%1], 16;" :: "r"(sa), "l"(g));
}
__device__ __forceinline__ void cpcommit() { asm volatile("cp.async.commit_group;"); }
__device__ __forceinline__ void cpwait0() {
    asm volatile("cp.async.wait_group 0;");
}
__device__ __forceinline__ unsigned ldflag(const unsigned* p) {
    unsigned v;
    asm volatile("ld.global.cg.u32 %0, [%1];" : "=r"(v) : "l"(p));
    return v;
}

// ---------------------------------------------------------------------------
// Kernel A: xproj = xs @ Wih  (bias folded into scan epilogue)
// 128x128x32 tiles, tf32 wmma, register double-buffered global loads.
// ---------------------------------------------------------------------------
__global__ void __launch_bounds__(256) xproj_gemm(const float* __restrict__ xs,
                                                  const float* __restrict__ Wih,
                                                  float* __restrict__ C) {
    __shared__ float As[128 * 36];
    __shared__ float Bs[32 * 136];

    const int tid = threadIdx.x;
    const int m0  = blockIdx.y * 128;
    const int n0  = blockIdx.x * 128;
    const int w   = tid >> 5;
    const int wm  = w >> 1;
    const int wn  = w & 1;

    wmma::fragment<wmma::accumulator, 16, 16, 8, float> cf[2][4];
#pragma unroll
    for (int i = 0; i < 2; i++)
#pragma unroll
        for (int j = 0; j < 4; j++) wmma::fill_fragment(cf[i][j], 0.0f);

    float4 a4[4], b4[4];
#pragma unroll
    for (int i = 0; i < 4; i++) {
        int idx = tid + i * 256;
        int r = idx >> 3, q = (idx & 7) * 4;
        a4[i] = *reinterpret_cast<const float4*>(xs + (size_t)(m0 + r) * H_SZ + q);
    }
#pragma unroll
    for (int i = 0; i < 4; i++) {
        int idx = tid + i * 256;
        int r = idx >> 5, q = (idx & 31) * 4;
        b4[i] = *reinterpret_cast<const float4*>(Wih + (size_t)r * H_SZ + n0 + q);
    }

    for (int kt = 0; kt < H_SZ; kt += 32) {
#pragma unroll
        for (int i = 0; i < 4; i++) {
            int idx = tid + i * 256;
            int r = idx >> 3, q = (idx & 7) * 4;
            float4 o;
            o.x = wmma::__float_to_tf32(a4[i].x);
            o.y = wmma::__float_to_tf32(a4[i].y);
            o.z = wmma::__float_to_tf32(a4[i].z);
            o.w = wmma::__float_to_tf32(a4[i].w);
            *reinterpret_cast<float4*>(As + r * 36 + q) = o;
        }
#pragma unroll
        for (int i = 0; i < 4; i++) {
            int idx = tid + i * 256;
            int r = idx >> 5, q = (idx & 31) * 4;
            float4 o;
            o.x = wmma::__float_to_tf32(b4[i].x);
            o.y = wmma::__float_to_tf32(b4[i].y);
            o.z = wmma::__float_to_tf32(b4[i].z);
            o.w = wmma::__float_to_tf32(b4[i].w);
            *reinterpret_cast<float4*>(Bs + r * 136 + q) = o;
        }
        __syncthreads();

        if (kt + 32 < H_SZ) {
#pragma unroll
            for (int i = 0; i < 4; i++) {
                int idx = tid + i * 256;
                int r = idx >> 3, q = (idx & 7) * 4;
                a4[i] = *reinterpret_cast<const float4*>(
                    xs + (size_t)(m0 + r) * H_SZ + kt + 32 + q);
            }
#pragma unroll
            for (int i = 0; i < 4; i++) {
                int idx = tid + i * 256;
                int r = idx >> 5, q = (idx & 31) * 4;
                b4[i] = *reinterpret_cast<const float4*>(
                    Wih + (size_t)(kt + 32 + r) * H_SZ + n0 + q);
            }
        }

#pragma unroll
        for (int kk = 0; kk < 4; kk++) {
            wmma::fragment<wmma::matrix_a, 16, 16, 8, wmma::precision::tf32, wmma::row_major> af[2];
            wmma::fragment<wmma::matrix_b, 16, 16, 8, wmma::precision::tf32, wmma::row_major> bf[4];
            wmma::load_matrix_sync(af[0], As + (wm * 32 + 0)  * 36 + kk * 8, 36);
            wmma::load_matrix_sync(af[1], As + (wm * 32 + 16) * 36 + kk * 8, 36);
#pragma unroll
            for (int j = 0; j < 4; j++)
                wmma::load_matrix_sync(bf[j], Bs + (kk * 8) * 136 + wn * 64 + j * 16, 136);
#pragma unroll
            for (int i = 0; i < 2; i++)
#pragma unroll
                for (int j = 0; j < 4; j++)
                    wmma::mma_sync(cf[i][j], af[i], bf[j], cf[i][j]);
        }
        __syncthreads();
    }

#pragma unroll
    for (int i = 0; i < 2; i++)
#pragma unroll
        for (int j = 0; j < 4; j++)
            wmma::store_matrix_sync(
                C + (size_t)(m0 + wm * 32 + i * 16) * H_SZ + n0 + wn * 64 + j * 16,
                cf[i][j], H_SZ, wmma::mem_row_major);
}

// ---------------------------------------------------------------------------
// Kernel B: persistent RNN scan, warp-autonomous chunks.
// Block bid: rb = bid&3 (16 batch rows), jb = bid>>2 (32 output cols).
// Warp w owns k-chunk w: spins on its 4 producer flags, cp.asyncs its own
// 16x128 h slice, runs its own MMAs. Only 2 block barriers per step.
// outs[t] holds xproj before step t, tf32-rounded h after.
// ---------------------------------------------------------------------------
__global__ void __launch_bounds__(256) rnn_scan(const float* __restrict__ init,
                                                const float* __restrict__ Whh,
                                                const float* __restrict__ bih,
                                                const float* __restrict__ bhh,
                                                float* __restrict__ outs,
                                                float* __restrict__ carry) {
    extern __shared__ float sm[];
    float* WhhS  = sm;                           // 1024*36      = 36864 f (147456 B)
    float* bufs  = WhhS + H_SZ * WST;            // 8 * 16*132   = 16896 f (67584 B)
    float* stage = bufs + NCH * RSZ * AST;       // 8 * 16*32    =  4096 f (16384 B)

    const int tid  = threadIdx.x, bid = blockIdx.x;
    const int rb   = bid & 3, jb = bid >> 2;
    const int r0   = rb * RSZ, j0 = jb * CSZ;
    const int w    = tid >> 5, lane = tid & 31;
    const int col  = tid & 31;                   // epilogue column (same both halves)

    const unsigned base = ldflag(&g_flags[bid]); // replay-safe epoch
    const float bsum = bih[j0 + col] + bhh[j0 + col];

    float* buf = bufs + w * (RSZ * AST);         // this warp's chunk buffer
    const unsigned pflag = (((unsigned)(w * 4 + (lane & 3))) << 2) | (unsigned)rb;

    // Load persistent Whh column slice (rounded to tf32)
#pragma unroll
    for (int i = 0; i < 32; i++) {
        int idx = tid + i * 256;
        int r = idx >> 3, q = (idx & 7) * 4;
        float4 v = *reinterpret_cast<const float4*>(Whh + (size_t)r * H_SZ + j0 + q);
        float4 o;
        o.x = wmma::__float_to_tf32(v.x);
        o.y = wmma::__float_to_tf32(v.y);
        o.z = wmma::__float_to_tf32(v.z);
        o.w = wmma::__float_to_tf32(v.w);
        *reinterpret_cast<float4*>(WhhS + r * WST + q) = o;
    }
    __syncthreads();

#pragma unroll 1
    for (int t = 0; t < T_STEPS; t++) {
        const float* hsrc = t ? (outs + (size_t)(t - 1) * BH) : init;

        // prefetch own xproj tile (own block's tile; no cross-block dep)
        const size_t xoff0 = (size_t)t * BH + (size_t)(r0 + (tid >> 5)) * H_SZ + j0 + col;
        const size_t xoff1 = xoff0 + 8 * H_SZ;
        const float xp0 = __ldcg(outs + xoff0);
        const float xp1 = __ldcg(outs + xoff1);

        // warp-local wait: only the 4 producers of this chunk's columns
        if (t > 0) {
            while (__any_sync(0xffffffffu,
                              (int)(ldflag(&g_flags[pflag]) - base) < t)) {
                __nanosleep(32);
            }
        }

        // warp-local load of its 16x128 h slice (8KB, 16 cp16/lane)
#pragma unroll
        for (int i = 0; i < 16; i++) {
            int idx = lane + i * 32;             // 0..511
            int r = idx >> 5, u = idx & 31;
            cp16(buf + r * AST + u * 4,
                 hsrc + (size_t)(r0 + r) * H_SZ + w * KCH + u * 4);
        }
        cpcommit();
        cpwait0();
        __syncwarp();

        // warp-local MMA: 16 k-steps x 2 col tiles, 2 independent accumulators
        wmma::fragment<wmma::accumulator, 16, 16, 8, float> acc0, acc1;
        wmma::fill_fragment(acc0, 0.0f);
        wmma::fill_fragment(acc1, 0.0f);
#pragma unroll
        for (int kk = 0; kk < 16; kk++) {
            wmma::fragment<wmma::matrix_a, 16, 16, 8, wmma::precision::tf32, wmma::row_major> af;
            wmma::fragment<wmma::matrix_b, 16, 16, 8, wmma::precision::tf32, wmma::row_major> bf0, bf1;
            wmma::load_matrix_sync(af, buf + kk * 8, AST);
            wmma::load_matrix_sync(bf0, WhhS + (w * KCH + kk * 8) * WST + 0,  WST);
            wmma::load_matrix_sync(bf1, WhhS + (w * KCH + kk * 8) * WST + 16, WST);
            wmma::mma_sync(acc0, af, bf0, acc0);
            wmma::mma_sync(acc1, af, bf1, acc1);
        }

        // publish partials (own region; prev-step readers retired by epilogue bar)
        wmma::store_matrix_sync(stage + w * (RSZ * CSZ) + 0,  acc0, CSZ, wmma::mem_row_major);
        wmma::store_matrix_sync(stage + w * (RSZ * CSZ) + 16, acc1, CSZ, wmma::mem_row_major);
        __syncthreads();

        // epilogue: h = tf32(tanh(sum_8_partials + xproj + bias)), in-place
#pragma unroll
        for (int i = 0; i < 2; i++) {
            int s = tid + i * 256;
            int r = s >> 5;
            float v = (i == 0 ? xp0 : xp1) + bsum;
#pragma unroll
            for (int k = 0; k < NCH; k++)
                v += stage[k * (RSZ * CSZ) + r * CSZ + col];
            v = wmma::__float_to_tf32(tanhf(v));
            size_t off = (size_t)t * BH + (size_t)(r0 + r) * H_SZ + j0 + col;
            __stcg(outs + off, v);
            if (carry != nullptr && t == T_STEPS - 1)
                __stcg(carry + (size_t)(r0 + r) * H_SZ + j0 + col, v);
        }
        __syncthreads();

        if (tid == 0) {
            __threadfence();
            atomicExch(&g_flags[bid], base + (unsigned)(t + 1));
        }
    }
}

// ---------------------------------------------------------------------------
extern "C" void kernel_launch(void* const* d_in, const int* in_sizes, int n_in,
                              void* d_out, int out_size) {
    const float* init = (const float*)d_in[0];
    const float* xs   = (const float*)d_in[1];
    const float* Wih  = (const float*)d_in[2];
    const float* bih  = (const float*)d_in[3];
    const float* Whh  = (const float*)d_in[4];
    const float* bhh  = (const float*)d_in[5];

    float* out   = (float*)d_out;
    float* carry = nullptr;
    float* outs;
    if (out_size == BH + TBH) { carry = out; outs = out + BH; }
    else                      { outs = out; }

    // 1) xproj = xs @ Wih  (into outs, consumed in-place by the scan)
    xproj_gemm<<<dim3(H_SZ / 128, (T_STEPS * B_SZ) / 128), 256>>>(xs, Wih, outs);

    // 2) persistent warp-autonomous scan (fuses carry write at t=T-1)
    int smem = (H_SZ * WST + NCH * RSZ * AST + NCH * RSZ * CSZ) * (int)sizeof(float);
    cudaFuncSetAttribute(rnn_scan, cudaFuncAttributeMaxDynamicSharedMemorySize, smem);
    rnn_scan<<<NBLK, 256, smem>>>(init, Whh, bih, bhh, outs, carry);
}

// round 4
// speedup vs baseline: 4.2901x; 1.1554x over previous
#include <cuda_runtime.h>
#include <mma.h>
#include <cstdint>

using namespace nvcuda;

#define T_STEPS 1024
#define B_SZ    64
#define H_SZ    1024
#define BH      (B_SZ * H_SZ)          /* 65536 */
#define TBH     (T_STEPS * BH)         /* 67108864 */

// ---------------- scan config ----------------
#define RSZ  16          // batch rows per block
#define CSZ  32          // output cols per block
#define NBLK 128         // (64/RSZ) * (1024/CSZ)
#define KCH  128         // k-chunk (one per warp)
#define NCH  8
#define AST  132         // h chunk smem row stride (pad)
#define WST  36          // Whh smem row stride (pad)

__device__ unsigned g_flags[NBLK];

// ---------------- asm helpers ----------------
__device__ __forceinline__ void cp16(float* s, const float* g) {
    unsigned sa = (unsigned)__cvta_generic_to_shared(s);
    asm volatile("cp.async.cg.shared.global [%0], [%1], 16;" :: "r"(sa), "l"(g));
}
__device__ __forceinline__ void cpcommit() { asm volatile("cp.async.commit_group;"); }
__device__ __forceinline__ void cpwait0() { asm volatile("cp.async.wait_group 0;"); }
__device__ __forceinline__ unsigned ldflag(const unsigned* p) {
    unsigned v;
    asm volatile("ld.global.cg.u32 %0, [%1];" : "=r"(v) : "l"(p));
    return v;
}
__device__ __forceinline__ void relexch(unsigned* p, unsigned v) {
    unsigned old;
    asm volatile("atom.release.gpu.global.exch.b32 %0, [%1], %2;"
                 : "=r"(old) : "l"(p), "r"(v) : "memory");
}

// ---------------------------------------------------------------------------
// Kernel A: xproj = xs @ Wih  (bias folded into scan epilogue)
// ---------------------------------------------------------------------------
__global__ void __launch_bounds__(256) xproj_gemm(const float* __restrict__ xs,
                                                  const float* __restrict__ Wih,
                                                  float* __restrict__ C) {
    __shared__ float As[128 * 36];
    __shared__ float Bs[32 * 136];

    const int tid = threadIdx.x;
    const int m0  = blockIdx.y * 128;
    const int n0  = blockIdx.x * 128;
    const int w   = tid >> 5;
    const int wm  = w >> 1;
    const int wn  = w & 1;

    wmma::fragment<wmma::accumulator, 16, 16, 8, float> cf[2][4];
#pragma unroll
    for (int i = 0; i < 2; i++)
#pragma unroll
        for (int j = 0; j < 4; j++) wmma::fill_fragment(cf[i][j], 0.0f);

    float4 a4[4], b4[4];
#pragma unroll
    for (int i = 0; i < 4; i++) {
        int idx = tid + i * 256;
        int r = idx >> 3, q = (idx & 7) * 4;
        a4[i] = *reinterpret_cast<const float4*>(xs + (size_t)(m0 + r) * H_SZ + q);
    }
#pragma unroll
    for (int i = 0; i < 4; i++) {
        int idx = tid + i * 256;
        int r = idx >> 5, q = (idx & 31) * 4;
        b4[i] = *reinterpret_cast<const float4*>(Wih + (size_t)r * H_SZ + n0 + q);
    }

    for (int kt = 0; kt < H_SZ; kt += 32) {
#pragma unroll
        for (int i = 0; i < 4; i++) {
            int idx = tid + i * 256;
            int r = idx >> 3, q = (idx & 7) * 4;
            float4 o;
            o.x = wmma::__float_to_tf32(a4[i].x);
            o.y = wmma::__float_to_tf32(a4[i].y);
            o.z = wmma::__float_to_tf32(a4[i].z);
            o.w = wmma::__float_to_tf32(a4[i].w);
            *reinterpret_cast<float4*>(As + r * 36 + q) = o;
        }
#pragma unroll
        for (int i = 0; i < 4; i++) {
            int idx = tid + i * 256;
            int r = idx >> 5, q = (idx & 31) * 4;
            float4 o;
            o.x = wmma::__float_to_tf32(b4[i].x);
            o.y = wmma::__float_to_tf32(b4[i].y);
            o.z = wmma::__float_to_tf32(b4[i].z);
            o.w = wmma::__float_to_tf32(b4[i].w);
            *reinterpret_cast<float4*>(Bs + r * 136 + q) = o;
        }
        __syncthreads();

        if (kt + 32 < H_SZ) {
#pragma unroll
            for (int i = 0; i < 4; i++) {
                int idx = tid + i * 256;
                int r = idx >> 3, q = (idx & 7) * 4;
                a4[i] = *reinterpret_cast<const float4*>(
                    xs + (size_t)(m0 + r) * H_SZ + kt + 32 + q);
            }
#pragma unroll
            for (int i = 0; i < 4; i++) {
                int idx = tid + i * 256;
                int r = idx >> 5, q = (idx & 31) * 4;
                b4[i] = *reinterpret_cast<const float4*>(
                    Wih + (size_t)(kt + 32 + r) * H_SZ + n0 + q);
            }
        }

#pragma unroll
        for (int kk = 0; kk < 4; kk++) {
            wmma::fragment<wmma::matrix_a, 16, 16, 8, wmma::precision::tf32, wmma::row_major> af[2];
            wmma::fragment<wmma::matrix_b, 16, 16, 8, wmma::precision::tf32, wmma::row_major> bf[4];
            wmma::load_matrix_sync(af[0], As + (wm * 32 + 0)  * 36 + kk * 8, 36);
            wmma::load_matrix_sync(af[1], As + (wm * 32 + 16) * 36 + kk * 8, 36);
#pragma unroll
            for (int j = 0; j < 4; j++)
                wmma::load_matrix_sync(bf[j], Bs + (kk * 8) * 136 + wn * 64 + j * 16, 136);
#pragma unroll
            for (int i = 0; i < 2; i++)
#pragma unroll
                for (int j = 0; j < 4; j++)
                    wmma::mma_sync(cf[i][j], af[i], bf[j], cf[i][j]);
        }
        __syncthreads();
    }

#pragma unroll
    for (int i = 0; i < 2; i++)
#pragma unroll
        for (int j = 0; j < 4; j++)
            wmma::store_matrix_sync(
                C + (size_t)(m0 + wm * 32 + i * 16) * H_SZ + n0 + wn * 64 + j * 16,
                cf[i][j], H_SZ, wmma::mem_row_major);
}

// ---------------------------------------------------------------------------
// Kernel B: persistent RNN scan, warp-autonomous chunks, register-resident Whh.
// Block bid: rb = bid&3 (16 batch rows), jb = bid>>2 (32 output cols).
// Warp w owns k-chunk c=(w+jb)&7: its Whh fragments live in REGISTERS for all
// 1024 steps; per step it spins on its 4 producer flags (lanes 0-3 only),
// cp.asyncs its 16x128 h slice, runs 16 MMA pairs. 2 block barriers/step.
// ---------------------------------------------------------------------------
__global__ void __launch_bounds__(256) rnn_scan(const float* __restrict__ init,
                                                const float* __restrict__ Whh,
                                                const float* __restrict__ bih,
                                                const float* __restrict__ bhh,
                                                float* __restrict__ outs,
                                                float* __restrict__ carry) {
    extern __shared__ float sm[];
    float* WhhS  = sm;                           // 1024*36 f
    float* bufs  = WhhS + H_SZ * WST;            // 8*16*132 f
    float* stage = bufs + NCH * RSZ * AST;       // 8*16*32 f

    const int tid  = threadIdx.x, bid = blockIdx.x;
    const int rb   = bid & 3, jb = bid >> 2;
    const int r0   = rb * RSZ, j0 = jb * CSZ;
    const int w    = tid >> 5, lane = tid & 31;
    const int c    = (w + jb) & 7;               // staggered chunk ownership
    const int col  = lane;

    const unsigned base = ldflag(&g_flags[bid]); // replay-safe epoch
    const float bsum = bih[j0 + col] + bhh[j0 + col];

    float* buf = bufs + w * (RSZ * AST);
    const unsigned* pflag = &g_flags[((unsigned)(c * 4 + lane) << 2) | (unsigned)rb];

    // Stage Whh column slice into smem (tf32-rounded)
#pragma unroll
    for (int i = 0; i < 32; i++) {
        int idx = tid + i * 256;
        int r = idx >> 3, q = (idx & 7) * 4;
        float4 v = *reinterpret_cast<const float4*>(Whh + (size_t)r * H_SZ + j0 + q);
        float4 o;
        o.x = wmma::__float_to_tf32(v.x);
        o.y = wmma::__float_to_tf32(v.y);
        o.z = wmma::__float_to_tf32(v.z);
        o.w = wmma::__float_to_tf32(v.w);
        *reinterpret_cast<float4*>(WhhS + r * WST + q) = o;
    }
    __syncthreads();

    // Hoist this warp's Whh fragments into registers — persistent for all steps
    wmma::fragment<wmma::matrix_b, 16, 16, 8, wmma::precision::tf32, wmma::row_major> Bf0[16], Bf1[16];
#pragma unroll
    for (int kk = 0; kk < 16; kk++) {
        wmma::load_matrix_sync(Bf0[kk], WhhS + (c * KCH + kk * 8) * WST + 0,  WST);
        wmma::load_matrix_sync(Bf1[kk], WhhS + (c * KCH + kk * 8) * WST + 16, WST);
    }

#pragma unroll 1
    for (int t = 0; t < T_STEPS; t++) {
        const float* hsrc = t ? (outs + (size_t)(t - 1) * BH) : init;

        // prefetch own xproj tile (latency hidden under spin)
        const size_t xoff0 = (size_t)t * BH + (size_t)(r0 + w) * H_SZ + j0 + col;
        const size_t xoff1 = xoff0 + 8 * H_SZ;
        const float xp0 = __ldcg(outs + xoff0);
        const float xp1 = __ldcg(outs + xoff1);

        // warp-local wait on the 4 producers of chunk c (lanes 0-3 poll)
        if (t > 0) {
            for (;;) {
                int ok = (lane < 4) ? ((int)(ldflag(pflag) - base) >= t) : 1;
                if (__all_sync(0xffffffffu, ok)) break;
                __nanosleep(20);
            }
        }

        // warp-local load of its 16x128 h slice (8KB)
#pragma unroll
        for (int i = 0; i < 16; i++) {
            int idx = lane + i * 32;
            int r = idx >> 5, u = idx & 31;
            cp16(buf + r * AST + u * 4,
                 hsrc + (size_t)(r0 + r) * H_SZ + c * KCH + u * 4);
        }
        cpcommit();
        cpwait0();
        __syncwarp();

        // 16 k-steps, B from registers, 2 independent accumulators
        wmma::fragment<wmma::accumulator, 16, 16, 8, float> acc0, acc1;
        wmma::fill_fragment(acc0, 0.0f);
        wmma::fill_fragment(acc1, 0.0f);
#pragma unroll
        for (int kk = 0; kk < 16; kk++) {
            wmma::fragment<wmma::matrix_a, 16, 16, 8, wmma::precision::tf32, wmma::row_major> af;
            wmma::load_matrix_sync(af, buf + kk * 8, AST);
            wmma::mma_sync(acc0, af, Bf0[kk], acc0);
            wmma::mma_sync(acc1, af, Bf1[kk], acc1);
        }

        wmma::store_matrix_sync(stage + w * (RSZ * CSZ) + 0,  acc0, CSZ, wmma::mem_row_major);
        wmma::store_matrix_sync(stage + w * (RSZ * CSZ) + 16, acc1, CSZ, wmma::mem_row_major);
        __syncthreads();

        // epilogue: h = tf32(tanh(sum_8_partials + xproj + bias)), in-place
#pragma unroll
        for (int i = 0; i < 2; i++) {
            int s = tid + i * 256;
            int r = s >> 5;
            float v = (i == 0 ? xp0 : xp1) + bsum;
#pragma unroll
            for (int k = 0; k < NCH; k++)
                v += stage[k * (RSZ * CSZ) + r * CSZ + col];
            v = wmma::__float_to_tf32(tanhf(v));
            size_t off = (size_t)t * BH + (size_t)(r0 + r) * H_SZ + j0 + col;
            __stcg(outs + off, v);
            if (carry != nullptr && t == T_STEPS - 1)
                __stcg(carry + (size_t)(r0 + r) * H_SZ + j0 + col, v);
        }
        __syncthreads();

        if (tid == 0) relexch(&g_flags[bid], base + (unsigned)(t + 1));
    }
}

// ---------------------------------------------------------------------------
extern "C" void kernel_launch(void* const* d_in, const int* in_sizes, int n_in,
                              void* d_out, int out_size) {
    const float* init = (const float*)d_in[0];
    const float* xs   = (const float*)d_in[1];
    const float* Wih  = (const float*)d_in[2];
    const float* bih  = (const float*)d_in[3];
    const float* Whh  = (const float*)d_in[4];
    const float* bhh  = (const float*)d_in[5];

    float* out   = (float*)d_out;
    float* carry = nullptr;
    float* outs;
    if (out_size == BH + TBH) { carry = out; outs = out + BH; }
    else                      { outs = out; }

    xproj_gemm<<<dim3(H_SZ / 128, (T_STEPS * B_SZ) / 128), 256>>>(xs, Wih, outs);

    int smem = (H_SZ * WST + NCH * RSZ * AST + NCH * RSZ * CSZ) * (int)sizeof(float);
    cudaFuncSetAttribute(rnn_scan, cudaFuncAttributeMaxDynamicSharedMemorySize, smem);
    rnn_scan<<<NBLK, 256, smem>>>(init, Whh, bih, bhh, outs, carry);
}

// round 5
// speedup vs baseline: 5.6549x; 1.3181x over previous
#include <cuda_runtime.h>
#include <mma.h>
#include <cstdint>

using namespace nvcuda;

#define T_STEPS 1024
#define B_SZ    64
#define H_SZ    1024
#define BH      (B_SZ * H_SZ)          /* 65536 */
#define TBH     (T_STEPS * BH)

// ---------------- scan config ----------------
#define RSZ   16         // batch rows per block
#define CSZ   32         // output cols per block
#define NBLK  128        // 4 row-groups x 32 col-blocks
#define KCH   64         // k columns per warp chunk
#define NWARP 16
#define SST   36         // stage row stride (floats, 8B-aligned, conflict-light)

__device__ unsigned g_flags[NBLK];
__device__ __align__(16) float g_hswz[2][BH];   // fragment-major h ping-pong

// ---------------- asm helpers ----------------
__device__ __forceinline__ unsigned ldacq(const unsigned* p) {
    unsigned v;
    asm volatile("ld.acquire.gpu.global.u32 %0, [%1];" : "=r"(v) : "l"(p));
    return v;
}
__device__ __forceinline__ unsigned ldflag(const unsigned* p) {
    unsigned v;
    asm volatile("ld.global.cg.u32 %0, [%1];" : "=r"(v) : "l"(p));
    return v;
}
__device__ __forceinline__ void relexch(unsigned* p, unsigned v) {
    unsigned old;
    asm volatile("atom.release.gpu.global.exch.b32 %0, [%1], %2;"
                 : "=r"(old) : "l"(p), "r"(v) : "memory");
}
__device__ __forceinline__ void mma_tf32(float acc[4], const uint4& a, const unsigned b[2]) {
    asm volatile("mma.sync.aligned.m16n8k8.row.col.f32.tf32.tf32.f32 "
                 "{%0,%1,%2,%3}, {%4,%5,%6,%7}, {%8,%9}, {%0,%1,%2,%3};"
                 : "+f"(acc[0]), "+f"(acc[1]), "+f"(acc[2]), "+f"(acc[3])
                 : "r"(a.x), "r"(a.y), "r"(a.z), "r"(a.w), "r"(b[0]), "r"(b[1]));
}

// ---------------------------------------------------------------------------
// Kernel A: xproj = xs @ Wih  (bias folded into scan epilogue)
// ---------------------------------------------------------------------------
__global__ void __launch_bounds__(256) xproj_gemm(const float* __restrict__ xs,
                                                  const float* __restrict__ Wih,
                                                  float* __restrict__ C) {
    __shared__ float As[128 * 36];
    __shared__ float Bs[32 * 136];

    const int tid = threadIdx.x;
    const int m0  = blockIdx.y * 128;
    const int n0  = blockIdx.x * 128;
    const int w   = tid >> 5;
    const int wm  = w >> 1;
    const int wn  = w & 1;

    wmma::fragment<wmma::accumulator, 16, 16, 8, float> cf[2][4];
#pragma unroll
    for (int i = 0; i < 2; i++)
#pragma unroll
        for (int j = 0; j < 4; j++) wmma::fill_fragment(cf[i][j], 0.0f);

    float4 a4[4], b4[4];
#pragma unroll
    for (int i = 0; i < 4; i++) {
        int idx = tid + i * 256;
        int r = idx >> 3, q = (idx & 7) * 4;
        a4[i] = *reinterpret_cast<const float4*>(xs + (size_t)(m0 + r) * H_SZ + q);
    }
#pragma unroll
    for (int i = 0; i < 4; i++) {
        int idx = tid + i * 256;
        int r = idx >> 5, q = (idx & 31) * 4;
        b4[i] = *reinterpret_cast<const float4*>(Wih + (size_t)r * H_SZ + n0 + q);
    }

    for (int kt = 0; kt < H_SZ; kt += 32) {
#pragma unroll
        for (int i = 0; i < 4; i++) {
            int idx = tid + i * 256;
            int r = idx >> 3, q = (idx & 7) * 4;
            float4 o;
            o.x = wmma::__float_to_tf32(a4[i].x);
            o.y = wmma::__float_to_tf32(a4[i].y);
            o.z = wmma::__float_to_tf32(a4[i].z);
            o.w = wmma::__float_to_tf32(a4[i].w);
            *reinterpret_cast<float4*>(As + r * 36 + q) = o;
        }
#pragma unroll
        for (int i = 0; i < 4; i++) {
            int idx = tid + i * 256;
            int r = idx >> 5, q = (idx & 31) * 4;
            float4 o;
            o.x = wmma::__float_to_tf32(b4[i].x);
            o.y = wmma::__float_to_tf32(b4[i].y);
            o.z = wmma::__float_to_tf32(b4[i].z);
            o.w = wmma::__float_to_tf32(b4[i].w);
            *reinterpret_cast<float4*>(Bs + r * 136 + q) = o;
        }
        __syncthreads();

        if (kt + 32 < H_SZ) {
#pragma unroll
            for (int i = 0; i < 4; i++) {
                int idx = tid + i * 256;
                int r = idx >> 3, q = (idx & 7) * 4;
                a4[i] = *reinterpret_cast<const float4*>(
                    xs + (size_t)(m0 + r) * H_SZ + kt + 32 + q);
            }
#pragma unroll
            for (int i = 0; i < 4; i++) {
                int idx = tid + i * 256;
                int r = idx >> 5, q = (idx & 31) * 4;
                b4[i] = *reinterpret_cast<const float4*>(
                    Wih + (size_t)(kt + 32 + r) * H_SZ + n0 + q);
            }
        }

#pragma unroll
        for (int kk = 0; kk < 4; kk++) {
            wmma::fragment<wmma::matrix_a, 16, 16, 8, wmma::precision::tf32, wmma::row_major> af[2];
            wmma::fragment<wmma::matrix_b, 16, 16, 8, wmma::precision::tf32, wmma::row_major> bf[4];
            wmma::load_matrix_sync(af[0], As + (wm * 32 + 0)  * 36 + kk * 8, 36);
            wmma::load_matrix_sync(af[1], As + (wm * 32 + 16) * 36 + kk * 8, 36);
#pragma unroll
            for (int j = 0; j < 4; j++)
                wmma::load_matrix_sync(bf[j], Bs + (kk * 8) * 136 + wn * 64 + j * 16, 136);
#pragma unroll
            for (int i = 0; i < 2; i++)
#pragma unroll
                for (int j = 0; j < 4; j++)
                    wmma::mma_sync(cf[i][j], af[i], bf[j], cf[i][j]);
        }
        __syncthreads();
    }

#pragma unroll
    for (int i = 0; i < 2; i++)
#pragma unroll
        for (int j = 0; j < 4; j++)
            wmma::store_matrix_sync(
                C + (size_t)(m0 + wm * 32 + i * 16) * H_SZ + n0 + wn * 64 + j * 16,
                cf[i][j], H_SZ, wmma::mem_row_major);
}

// ---------------------------------------------------------------------------
// Swizzle init -> g_hswz[1]  (acts as h_{-1}; slot (t+1)&1 is read at step t)
// fragment-major layout per (rb, chunk c, kstep kk): 32 lanes x 4 regs where
// reg order = [a0(g,tg), a1(g+8,tg), a2(g,tg+4), a3(g+8,tg+4)], lane = 4g+tg.
// ---------------------------------------------------------------------------
__global__ void swizzle_init(const float* __restrict__ init) {
    int idx = blockIdx.x * 256 + threadIdx.x;        // 0..65535
    int r = idx >> 10, gcol = idx & 1023;
    int rb = r >> 4, r16 = r & 15;
    int c = gcol >> 6, kk = (gcol >> 3) & 7, tcol = gcol & 7;
    int reg  = ((r16 >= 8) ? 1 : 0) | ((tcol >= 4) ? 2 : 0);
    int lane = 4 * (r16 & 7) + (tcol & 3);
    g_hswz[1][rb * 16384 + ((c * 8 + kk) * 32 + lane) * 4 + reg] =
        wmma::__float_to_tf32(init[idx]);
}

// ---------------------------------------------------------------------------
// Kernel B: persistent scan. 512 thr / 16 warps; warp owns 64-col k-chunk,
// Whh fragments in registers (64), A fragments via coalesced LDG.128 from the
// swizzled ping-pong buffer. 2 producer flags per warp, acquire-polled.
// ---------------------------------------------------------------------------
__global__ void __launch_bounds__(512) rnn_scan(const float* __restrict__ Whh,
                                                const float* __restrict__ bih,
                                                const float* __restrict__ bhh,
                                                float* __restrict__ outs,
                                                float* __restrict__ carry) {
    __shared__ float stage[NWARP * RSZ * SST];       // 36864 B

    const int tid = threadIdx.x, bid = blockIdx.x;
    const int rb = bid & 3, jb = bid >> 2;
    const int r0 = rb * RSZ, j0 = jb * CSZ;
    const int w = tid >> 5, lane = tid & 31;
    const int g = lane >> 2, tg = lane & 3;
    const int c = (w + jb) & 15;                     // staggered chunk
    const int er = tid >> 5, ec = lane;              // epilogue elem (16x32)

    const unsigned base = ldflag(&g_flags[bid]);
    const float bsum = bih[j0 + ec] + bhh[j0 + ec];

    // this thread's swizzle slot for its produced h element (er, j0+ec)
    const int pgc = j0 + ec;
    const int preg  = ((er >= 8) ? 1 : 0) | (((pgc & 7) >= 4) ? 2 : 0);
    const int plane = 4 * (er & 7) + (pgc & 3);
    const int swz_off = rb * 16384 +
        (((pgc >> 6) * 8 + ((pgc >> 3) & 7)) * 32 + plane) * 4 + preg;

    // 2 producer flags for chunk c (cols c*64..c*64+63 of row group rb)
    const unsigned* pflag =
        &g_flags[(((unsigned)(2 * c + (lane & 1))) << 2) | (unsigned)rb];

    // Whh fragments: 8 ksteps x 4 ntiles x 2 regs = 64 registers, persistent
    unsigned Bf[8][4][2];
#pragma unroll
    for (int kk = 0; kk < 8; kk++)
#pragma unroll
        for (int nt = 0; nt < 4; nt++) {
            int krow = c * KCH + kk * 8 + tg;
            int ncol = j0 + nt * 8 + g;
            Bf[kk][nt][0] = __float_as_uint(
                wmma::__float_to_tf32(Whh[(size_t)krow * H_SZ + ncol]));
            Bf[kk][nt][1] = __float_as_uint(
                wmma::__float_to_tf32(Whh[(size_t)(krow + 4) * H_SZ + ncol]));
        }

    float* stg = stage + w * (RSZ * SST);

#pragma unroll 1
    for (int t = 0; t < T_STEPS; t++) {
        // xproj element (latency hidden under poll/mma)
        const size_t ooff = (size_t)t * BH + (size_t)(r0 + er) * H_SZ + j0 + ec;
        const float xp = __ldcg(outs + ooff);

        if (t > 0) {
            for (;;) {
                int ok = (lane < 2) ? ((int)(ldacq(pflag) - base) >= t) : 1;
                if (__all_sync(0xffffffffu, ok)) break;
                __nanosleep(16);
            }
        }

        // A fragments: 8 coalesced LDG.128 from swizzled h_{t-1}
        const uint4* ap = reinterpret_cast<const uint4*>(
            g_hswz[(t + 1) & 1] + rb * 16384 + (c * 8) * 128) + lane;

        float acc[4][4] = {{0,0,0,0},{0,0,0,0},{0,0,0,0},{0,0,0,0}};
        uint4 av = __ldcg(ap);
#pragma unroll
        for (int kk = 0; kk < 8; kk++) {
            uint4 nx;
            if (kk < 7) nx = __ldcg(ap + (kk + 1) * 32);
#pragma unroll
            for (int nt = 0; nt < 4; nt++)
                mma_tf32(acc[nt], av, Bf[kk][nt]);
            av = nx;
        }

        // stage partials (pad stride 36 -> <=2-way conflicts)
#pragma unroll
        for (int nt = 0; nt < 4; nt++) {
            *reinterpret_cast<float2*>(stg + g * SST + nt * 8 + 2 * tg) =
                make_float2(acc[nt][0], acc[nt][1]);
            *reinterpret_cast<float2*>(stg + (g + 8) * SST + nt * 8 + 2 * tg) =
                make_float2(acc[nt][2], acc[nt][3]);
        }
        __syncthreads();

        // epilogue: reduce 16 partials, tanh, dual store (canonical + swizzle)
        float v = xp + bsum;
#pragma unroll
        for (int k = 0; k < NWARP; k++)
            v += stage[k * (RSZ * SST) + er * SST + ec];
        v = wmma::__float_to_tf32(tanhf(v));
        __stcg(outs + ooff, v);
        __stcg(&g_hswz[t & 1][swz_off], v);
        if (carry != nullptr && t == T_STEPS - 1)
            __stcg(carry + (size_t)(r0 + er) * H_SZ + j0 + ec, v);
        __syncthreads();

        if (tid == 0) relexch(&g_flags[bid], base + (unsigned)(t + 1));
    }
}

// ---------------------------------------------------------------------------
extern "C" void kernel_launch(void* const* d_in, const int* in_sizes, int n_in,
                              void* d_out, int out_size) {
    const float* init = (const float*)d_in[0];
    const float* xs   = (const float*)d_in[1];
    const float* Wih  = (const float*)d_in[2];
    const float* bih  = (const float*)d_in[3];
    const float* Whh  = (const float*)d_in[4];
    const float* bhh  = (const float*)d_in[5];

    float* out   = (float*)d_out;
    float* carry = nullptr;
    float* outs;
    if (out_size == BH + TBH) { carry = out; outs = out + BH; }
    else                      { outs = out; }

    swizzle_init<<<BH / 256, 256>>>(init);
    xproj_gemm<<<dim3(H_SZ / 128, (T_STEPS * B_SZ) / 128), 256>>>(xs, Wih, outs);
    rnn_scan<<<NBLK, 512>>>(Whh, bih, bhh, outs, carry);
}

// round 6
// speedup vs baseline: 5.7356x; 1.0143x over previous
#include <cuda_runtime.h>
#include <mma.h>
#include <cstdint>

using namespace nvcuda;

#define T_STEPS 1024
#define B_SZ    64
#define H_SZ    1024
#define BH      (B_SZ * H_SZ)          /* 65536 */
#define TBH     (T_STEPS * BH)

// ---------------- scan config ----------------
#define RSZ   16         // batch rows per block
#define CSZ   32         // output cols per block
#define NBLK  128        // 4 row-groups x 32 col-blocks
#define KCH   64         // k columns per warp chunk
#define NWARP 16
#define SST   36         // stage row stride (floats)
#define FPAD  32         // one flag per 128B L2 line

__device__ unsigned g_flags[NBLK * FPAD];
__device__ __align__(16) float g_hswz[2][BH];   // fragment-major h ping-pong

// ---------------- asm helpers ----------------
__device__ __forceinline__ unsigned ldacq(const unsigned* p) {
    unsigned v;
    asm volatile("ld.acquire.gpu.global.u32 %0, [%1];" : "=r"(v) : "l"(p));
    return v;
}
__device__ __forceinline__ unsigned ldflag(const unsigned* p) {
    unsigned v;
    asm volatile("ld.global.cg.u32 %0, [%1];" : "=r"(v) : "l"(p));
    return v;
}
__device__ __forceinline__ void strel(unsigned* p, unsigned v) {
    asm volatile("st.release.gpu.global.u32 [%0], %1;" :: "l"(p), "r"(v) : "memory");
}
__device__ __forceinline__ void mma_tf32(float acc[4], const uint4& a, const unsigned b[2]) {
    asm volatile("mma.sync.aligned.m16n8k8.row.col.f32.tf32.tf32.f32 "
                 "{%0,%1,%2,%3}, {%4,%5,%6,%7}, {%8,%9}, {%0,%1,%2,%3};"
                 : "+f"(acc[0]), "+f"(acc[1]), "+f"(acc[2]), "+f"(acc[3])
                 : "r"(a.x), "r"(a.y), "r"(a.z), "r"(a.w), "r"(b[0]), "r"(b[1]));
}

// ---------------------------------------------------------------------------
// Kernel A: xproj = xs @ Wih  (bias folded into scan epilogue)
// ---------------------------------------------------------------------------
__global__ void __launch_bounds__(256) xproj_gemm(const float* __restrict__ xs,
                                                  const float* __restrict__ Wih,
                                                  float* __restrict__ C) {
    __shared__ float As[128 * 36];
    __shared__ float Bs[32 * 136];

    const int tid = threadIdx.x;
    const int m0  = blockIdx.y * 128;
    const int n0  = blockIdx.x * 128;
    const int w   = tid >> 5;
    const int wm  = w >> 1;
    const int wn  = w & 1;

    wmma::fragment<wmma::accumulator, 16, 16, 8, float> cf[2][4];
#pragma unroll
    for (int i = 0; i < 2; i++)
#pragma unroll
        for (int j = 0; j < 4; j++) wmma::fill_fragment(cf[i][j], 0.0f);

    float4 a4[4], b4[4];
#pragma unroll
    for (int i = 0; i < 4; i++) {
        int idx = tid + i * 256;
        int r = idx >> 3, q = (idx & 7) * 4;
        a4[i] = *reinterpret_cast<const float4*>(xs + (size_t)(m0 + r) * H_SZ + q);
    }
#pragma unroll
    for (int i = 0; i < 4; i++) {
        int idx = tid + i * 256;
        int r = idx >> 5, q = (idx & 31) * 4;
        b4[i] = *reinterpret_cast<const float4*>(Wih + (size_t)r * H_SZ + n0 + q);
    }

    for (int kt = 0; kt < H_SZ; kt += 32) {
#pragma unroll
        for (int i = 0; i < 4; i++) {
            int idx = tid + i * 256;
            int r = idx >> 3, q = (idx & 7) * 4;
            float4 o;
            o.x = wmma::__float_to_tf32(a4[i].x);
            o.y = wmma::__float_to_tf32(a4[i].y);
            o.z = wmma::__float_to_tf32(a4[i].z);
            o.w = wmma::__float_to_tf32(a4[i].w);
            *reinterpret_cast<float4*>(As + r * 36 + q) = o;
        }
#pragma unroll
        for (int i = 0; i < 4; i++) {
            int idx = tid + i * 256;
            int r = idx >> 5, q = (idx & 31) * 4;
            float4 o;
            o.x = wmma::__float_to_tf32(b4[i].x);
            o.y = wmma::__float_to_tf32(b4[i].y);
            o.z = wmma::__float_to_tf32(b4[i].z);
            o.w = wmma::__float_to_tf32(b4[i].w);
            *reinterpret_cast<float4*>(Bs + r * 136 + q) = o;
        }
        __syncthreads();

        if (kt + 32 < H_SZ) {
#pragma unroll
            for (int i = 0; i < 4; i++) {
                int idx = tid + i * 256;
                int r = idx >> 3, q = (idx & 7) * 4;
                a4[i] = *reinterpret_cast<const float4*>(
                    xs + (size_t)(m0 + r) * H_SZ + kt + 32 + q);
            }
#pragma unroll
            for (int i = 0; i < 4; i++) {
                int idx = tid + i * 256;
                int r = idx >> 5, q = (idx & 31) * 4;
                b4[i] = *reinterpret_cast<const float4*>(
                    Wih + (size_t)(kt + 32 + r) * H_SZ + n0 + q);
            }
        }

#pragma unroll
        for (int kk = 0; kk < 4; kk++) {
            wmma::fragment<wmma::matrix_a, 16, 16, 8, wmma::precision::tf32, wmma::row_major> af[2];
            wmma::fragment<wmma::matrix_b, 16, 16, 8, wmma::precision::tf32, wmma::row_major> bf[4];
            wmma::load_matrix_sync(af[0], As + (wm * 32 + 0)  * 36 + kk * 8, 36);
            wmma::load_matrix_sync(af[1], As + (wm * 32 + 16) * 36 + kk * 8, 36);
#pragma unroll
            for (int j = 0; j < 4; j++)
                wmma::load_matrix_sync(bf[j], Bs + (kk * 8) * 136 + wn * 64 + j * 16, 136);
#pragma unroll
            for (int i = 0; i < 2; i++)
#pragma unroll
                for (int j = 0; j < 4; j++)
                    wmma::mma_sync(cf[i][j], af[i], bf[j], cf[i][j]);
        }
        __syncthreads();
    }

#pragma unroll
    for (int i = 0; i < 2; i++)
#pragma unroll
        for (int j = 0; j < 4; j++)
            wmma::store_matrix_sync(
                C + (size_t)(m0 + wm * 32 + i * 16) * H_SZ + n0 + wn * 64 + j * 16,
                cf[i][j], H_SZ, wmma::mem_row_major);
}

// ---------------------------------------------------------------------------
// Swizzle init -> g_hswz[1]  (slot (t+1)&1 is read at step t)
// ---------------------------------------------------------------------------
__global__ void swizzle_init(const float* __restrict__ init) {
    int idx = blockIdx.x * 256 + threadIdx.x;        // 0..65535
    int r = idx >> 10, gcol = idx & 1023;
    int rb = r >> 4, r16 = r & 15;
    int c = gcol >> 6, kk = (gcol >> 3) & 7, tcol = gcol & 7;
    int reg  = ((r16 >= 8) ? 1 : 0) | ((tcol >= 4) ? 2 : 0);
    int lane = 4 * (r16 & 7) + (tcol & 3);
    g_hswz[1][rb * 16384 + ((c * 8 + kk) * 32 + lane) * 4 + reg] =
        wmma::__float_to_tf32(init[idx]);
}

// ---------------------------------------------------------------------------
// Kernel B: persistent scan. 512 thr / 16 warps; warp owns 64-col k-chunk,
// Whh fragments in registers, A fragments via coalesced LDG.128 from the
// swizzled ping-pong buffer. Line-padded flags, .cg polls + one acquire.
// ---------------------------------------------------------------------------
__global__ void __launch_bounds__(512) rnn_scan(const float* __restrict__ Whh,
                                                const float* __restrict__ bih,
                                                const float* __restrict__ bhh,
                                                float* __restrict__ outs,
                                                float* __restrict__ carry) {
    __shared__ float stage[NWARP * RSZ * SST];       // 36864 B

    const int tid = threadIdx.x, bid = blockIdx.x;
    const int rb = bid & 3, jb = bid >> 2;
    const int r0 = rb * RSZ, j0 = jb * CSZ;
    const int w = tid >> 5, lane = tid & 31;
    const int g = lane >> 2, tg = lane & 3;
    const int c = (w + jb) & 15;                     // staggered chunk
    const int er = tid >> 5, ec = lane;              // epilogue elem (16x32)

    unsigned* myflag = &g_flags[bid * FPAD];
    const unsigned base = ldflag(myflag);
    const float bsum = bih[j0 + ec] + bhh[j0 + ec];

    // this thread's swizzle slot for its produced h element (er, j0+ec)
    const int pgc = j0 + ec;
    const int preg  = ((er >= 8) ? 1 : 0) | (((pgc & 7) >= 4) ? 2 : 0);
    const int plane = 4 * (er & 7) + (pgc & 3);
    const int swz_off = rb * 16384 +
        (((pgc >> 6) * 8 + ((pgc >> 3) & 7)) * 32 + plane) * 4 + preg;

    // 2 producer flags for chunk c (cols c*64..c*64+63 of row group rb)
    const unsigned* pflag =
        &g_flags[((((unsigned)(2 * c + (lane & 1))) << 2) | (unsigned)rb) * FPAD];

    // Whh fragments: 8 ksteps x 4 ntiles x 2 regs = 64 registers, persistent
    unsigned Bf[8][4][2];
#pragma unroll
    for (int kk = 0; kk < 8; kk++)
#pragma unroll
        for (int nt = 0; nt < 4; nt++) {
            int krow = c * KCH + kk * 8 + tg;
            int ncol = j0 + nt * 8 + g;
            Bf[kk][nt][0] = __float_as_uint(
                wmma::__float_to_tf32(Whh[(size_t)krow * H_SZ + ncol]));
            Bf[kk][nt][1] = __float_as_uint(
                wmma::__float_to_tf32(Whh[(size_t)(krow + 4) * H_SZ + ncol]));
        }

    float* stg = stage + w * (RSZ * SST);

#pragma unroll 1
    for (int t = 0; t < T_STEPS; t++) {
        // xproj element (latency hidden under poll/mma)
        const size_t ooff = (size_t)t * BH + (size_t)(r0 + er) * H_SZ + j0 + ec;
        const float xp = __ldcg(outs + ooff);

        if (t > 0) {
            for (;;) {
                int ok = (lane < 2) ? ((int)(ldflag(pflag) - base) >= t) : 1;
                if (__all_sync(0xffffffffu, ok)) break;
                __nanosleep(24);
            }
            if (lane < 2) (void)ldacq(pflag);   // one acquire after success
        }

        // A fragments: 8 coalesced LDG.128 from swizzled h_{t-1}
        const uint4* ap = reinterpret_cast<const uint4*>(
            g_hswz[(t + 1) & 1] + rb * 16384 + (c * 8) * 128) + lane;

        float acc[4][4] = {{0,0,0,0},{0,0,0,0},{0,0,0,0},{0,0,0,0}};
        uint4 av = __ldcg(ap);
#pragma unroll
        for (int kk = 0; kk < 8; kk++) {
            uint4 nx;
            if (kk < 7) nx = __ldcg(ap + (kk + 1) * 32);
#pragma unroll
            for (int nt = 0; nt < 4; nt++)
                mma_tf32(acc[nt], av, Bf[kk][nt]);
            av = nx;
        }

        // stage partials (pad stride 36 -> <=2-way conflicts)
#pragma unroll
        for (int nt = 0; nt < 4; nt++) {
            *reinterpret_cast<float2*>(stg + g * SST + nt * 8 + 2 * tg) =
                make_float2(acc[nt][0], acc[nt][1]);
            *reinterpret_cast<float2*>(stg + (g + 8) * SST + nt * 8 + 2 * tg) =
                make_float2(acc[nt][2], acc[nt][3]);
        }
        __syncthreads();

        // epilogue: reduce 16 partials, tanh, dual store (canonical + swizzle)
        float v = xp + bsum;
#pragma unroll
        for (int k = 0; k < NWARP; k++)
            v += stage[k * (RSZ * SST) + er * SST + ec];
        v = wmma::__float_to_tf32(tanhf(v));
        __stcg(outs + ooff, v);
        __stcg(&g_hswz[t & 1][swz_off], v);
        if (carry != nullptr && t == T_STEPS - 1)
            __stcg(carry + (size_t)(r0 + er) * H_SZ + j0 + ec, v);
        __syncthreads();

        if (tid == 0) strel(myflag, base + (unsigned)(t + 1));
    }
}

// ---------------------------------------------------------------------------
extern "C" void kernel_launch(void* const* d_in, const int* in_sizes, int n_in,
                              void* d_out, int out_size) {
    const float* init = (const float*)d_in[0];
    const float* xs   = (const float*)d_in[1];
    const float* Wih  = (const float*)d_in[2];
    const float* bih  = (const float*)d_in[3];
    const float* Whh  = (const float*)d_in[4];
    const float* bhh  = (const float*)d_in[5];

    float* out   = (float*)d_out;
    float* carry = nullptr;
    float* outs;
    if (out_size == BH + TBH) { carry = out; outs = out + BH; }
    else                      { outs = out; }

    swizzle_init<<<BH / 256, 256>>>(init);
    xproj_gemm<<<dim3(H_SZ / 128, (T_STEPS * B_SZ) / 128), 256>>>(xs, Wih, outs);
    rnn_scan<<<NBLK, 512>>>(Whh, bih, bhh, outs, carry);
}